// round 12
// baseline (speedup 1.0000x reference)
#include <cuda_runtime.h>

#define INV_CELL 20.0f
#define NTHREADS 128     // 4 warps; each warp owns 4 points
#define PTS 16           // points per block
#define WPTS 4           // points per warp
#define GR_STRIDE 49     // float4 per grad point-row (48 + 1 pad)
#define WARP_CHUNK (WPTS * GR_STRIDE)   // 196 float4 per warp

// Cubic B-spline basis + gradient for a single stencil offset m (0..3).
// x = f + 1 - m deterministically falls in branch: m=0 -> [1,2), m=1 -> [0,1),
// m=2 -> [-1,0), m=3 -> [-2,-1). Coefficient sets selected branch-free;
// FMA chains identical in shape to the reference polynomials.
__device__ __forceinline__ void spline1(float f, int m, float& b, float& db) {
    float x  = f + (float)(1 - m);
    float a3 = (m == 0) ? -1.0f/6.0f : (m == 1) ? 0.5f : (m == 2) ? -0.5f : 1.0f/6.0f;
    float a2 = (m == 0 || m == 3) ? 1.0f : -1.0f;
    float a1 = (m == 0) ? -2.0f : (m == 3) ? 2.0f : 0.0f;
    float a0 = (m == 0 || m == 3) ? 4.0f/3.0f : 2.0f/3.0f;
    float d2 = (m == 0) ? -0.5f : (m == 1) ? 1.5f : (m == 2) ? -1.5f : 0.5f;
    float d1 = (m == 0 || m == 3) ? 2.0f : -2.0f;
    float d0 = (m == 0) ? -2.0f : (m == 3) ? 2.0f : 0.0f;
    b  = ((a3 * x + a2) * x + a1) * x + a0;
    db = INV_CELL * ((d2 * x + d1) * x + d0);
}

// 256-bit streaming store (Blackwell sm_100+).
__device__ __forceinline__ void stg256_cs(float* p, const float v[8]) {
    asm volatile("st.global.cs.v8.f32 [%0], {%1,%2,%3,%4,%5,%6,%7,%8};"
                 :: "l"(p),
                    "f"(v[0]), "f"(v[1]), "f"(v[2]), "f"(v[3]),
                    "f"(v[4]), "f"(v[5]), "f"(v[6]), "f"(v[7])
                 : "memory");
}

__global__ void __launch_bounds__(NTHREADS, 12)
cubic_shape_kernel(const float* __restrict__ pos,
                   float* __restrict__ out_sf,
                   float* __restrict__ out_grad,
                   int n_points) {
    __shared__ float4 gr_s[4 * WARP_CHUNK];   // 12544 B, one chunk per warp

    int tid  = threadIdx.x;
    int w    = tid >> 5;       // warp id 0..3
    int lane = tid & 31;
    int gl   = lane >> 3;      // local point within warp 0..3
    int s    = lane & 7;
    int i    = s >> 1;         // x-stencil index owned (grad AND sf chunk s)
    int jh   = s & 1;          // y half owned: j in {2jh, 2jh+1}
    int wpt0 = blockIdx.x * PTS + w * WPTS;   // first point of this warp
    int n    = wpt0 + gl;

    float4* warp_s = gr_s + w * WARP_CHUNK;

    if (n < n_points) {
        float px = __ldg(&pos[n * 3 + 0]);
        float py = __ldg(&pos[n * 3 + 1]);
        float pz = __ldg(&pos[n * 3 + 2]);

        float rx = px * INV_CELL, ry = py * INV_CELL, rz = pz * INV_CELL;
        float fx = rx - floorf(rx);
        float fy = ry - floorf(ry);
        float fz = rz - floorf(rz);

        // z: all 4 offsets
        float bz[4], dbz[4];
#pragma unroll
        for (int m = 0; m < 4; m++) spline1(fz, m, bz[m], dbz[m]);

        // own x index and y pair
        float bxi, dbxi;  spline1(fx, i, bxi, dbxi);
        float by0, dby0;  spline1(fy, 2 * jh,     by0, dby0);
        float by1, dby1;  spline1(fy, 2 * jh + 1, by1, dby1);

        // sf v8 chunk s covers entries 8s..8s+7 == (i, {2jh,2jh+1}, k=0..3):
        // exactly this thread's grad ownership -> values fall out of bij.
        float sfv[8];

        // ---- grad: stage into this warp's smem chunk ----
#pragma unroll
        for (int t = 0; t < 2; t++) {
            int   j   = 2 * jh + t;
            float bj  = t ? by1  : by0;
            float dbj = t ? dby1 : dby0;
            float bij    = bxi * bj;
            float dbi_bj = dbxi * bj;
            float bi_dbj = bxi * dbj;

            float gg[12];
#pragma unroll
            for (int k = 0; k < 4; k++) {
                gg[k * 3 + 0] = dbi_bj * bz[k];
                gg[k * 3 + 1] = bi_dbj * bz[k];
                gg[k * 3 + 2] = bij * dbz[k];
                sfv[4 * t + k] = bij * bz[k];
            }
            int base = gl * GR_STRIDE + i * 12 + j * 3;
            warp_s[base + 0] = make_float4(gg[0], gg[1], gg[2],  gg[3]);
            warp_s[base + 1] = make_float4(gg[4], gg[5], gg[6],  gg[7]);
            warp_s[base + 2] = make_float4(gg[8], gg[9], gg[10], gg[11]);
        }

        // ---- sf: one perfectly coalesced 256-bit store per thread ----
        // Warp covers 4 consecutive points x 256B = 1024B contiguous.
        stg256_cs(out_sf + (size_t)n * 64 + s * 8, sfv);
    }
    __syncwarp();

    // ---- grad copy-out: warp-local, 3 x 256-bit coalesced streams ----
    // Warp covers v8 range [wpt0*24, wpt0*24 + 96).
    {
        int     wbase8 = wpt0 * 24;
        int     total8 = n_points * 24;
        float*  dstf   = out_grad;
        if (wbase8 + 96 <= total8) {
#pragma unroll
            for (int p = 0; p < 3; p++) {
                int idx8 = p * 32 + lane;            // 0..95
                int fq   = 2 * idx8;                 // float4 index 0..191
                int pf   = fq + fq / 48;             // padded smem index
                float4 a = warp_s[pf];
                float4 b = warp_s[pf + 1];           // adjacent: fq+1 never crosses pad
                float v[8] = {a.x, a.y, a.z, a.w, b.x, b.y, b.z, b.w};
                stg256_cs(dstf + (size_t)(wbase8 + idx8) * 8, v);
            }
        } else {
            // tail (never hit for N % PTS == 0): float4 granularity with guard
            float4* dst4   = reinterpret_cast<float4*>(out_grad);
            int     wbase4 = wpt0 * 48;
            int     total4 = n_points * 48;
#pragma unroll
            for (int p = 0; p < 6; p++) {
                int idx = p * 32 + lane;             // 0..191
                if (wbase4 + idx < total4)
                    __stcs(&dst4[wbase4 + idx], warp_s[idx + idx / 48]);
            }
        }
    }
}

extern "C" void kernel_launch(void* const* d_in, const int* in_sizes, int n_in,
                              void* d_out, int out_size) {
    const float* pos = (const float*)d_in[0];
    int n_points = in_sizes[0] / 3;

    float* out_sf   = (float*)d_out;                      // [N, 64]
    float* out_grad = out_sf + (size_t)n_points * 64;     // [N, 64, 3]

    int grid = (n_points + PTS - 1) / PTS;
    cubic_shape_kernel<<<grid, NTHREADS>>>(pos, out_sf, out_grad, n_points);
}